// round 10
// baseline (speedup 1.0000x reference)
#include <cuda_runtime.h>
#include <cuda_bf16.h>
#include <math.h>
#include <stdint.h>

#define VOCAB 100000
#define EMB   300
#define HID   256
#define BATCH 64
#define SEQ   512
#define NROWS (SEQ*BATCH)   /* 32768 */
#define GCOLS 2048          /* 2 dirs * 4 gates * 256 */
#define K3MAX 1536          /* max concatenated K (layer 1: 3*512) */

// ---------------- static scratch (no allocations allowed) -------------------
__device__ float d_G [(size_t)NROWS * GCOLS];     // gate preactivations
__device__ float d_Y1[(size_t)NROWS * 512];       // layer-1 output (t,b,2H)
__device__ __nv_bfloat16 d_A2[(size_t)NROWS * K3MAX];  // [Ahi|Alo|Ahi]
__device__ __nv_bfloat16 d_W2[(size_t)GCOLS * K3MAX];  // [Whi|Whi|Wlo]

// ---------------- packed fp32x2 helpers (lstm_rec dot phase) ----------------
__device__ __forceinline__ void fma2(unsigned long long& acc,
                                     unsigned long long a, unsigned long long b) {
    asm("fma.rn.f32x2 %0, %1, %2, %0;" : "+l"(acc) : "l"(a), "l"(b));
}
__device__ __forceinline__ float2 unpk(unsigned long long v) {
    float2 f;
    asm("mov.b64 {%0, %1}, %2;" : "=f"(f.x), "=f"(f.y) : "l"(v));
    return f;
}
// fast MUFU-based activations (~1e-6 rel err; avoids div.rn / precise tanhf)
__device__ __forceinline__ float fsigm(float x) {
    return __fdividef(1.f, 1.f + __expf(-x));
}
__device__ __forceinline__ float ftanh(float x) {
    return __fdividef(2.f, 1.f + __expf(-2.f * x)) - 1.f;
}

// ============================================================================
// conv_a: layer-0 input — emb gather -> split bf16 [hi|lo|hi], Kp=320, stride 960
// ============================================================================
__global__ void conv_a(const float* __restrict__ emb, const int* __restrict__ tokens)
{
    int r = blockIdx.x;                    // r = t*64 + b
    int b = r & 63, t = r >> 6;
    const float* src = emb + (size_t)tokens[b * SEQ + t] * EMB;
    __nv_bfloat16* row = d_A2 + (size_t)r * 960;
    for (int c = threadIdx.x; c < 320; c += blockDim.x) {
        float x = (c < EMB) ? src[c] : 0.f;
        __nv_bfloat16 h = __float2bfloat16(x);
        row[c]       = h;
        row[320 + c] = __float2bfloat16(x - __bfloat162float(h));
        row[640 + c] = h;
    }
}

__global__ void conv_w(const float* __restrict__ w, int layer)
{
    int r = blockIdx.x;                    // gate-column index (2048)
    int K, Kp, stride;
    if (layer == 0) { K = 300; Kp = 320; stride = 960; }
    else            { K = 512; Kp = 512; stride = 1536; }
    const float* src = w + (size_t)r * K;
    __nv_bfloat16* row = d_W2 + (size_t)r * stride;
    for (int c = threadIdx.x; c < Kp; c += blockDim.x) {
        float x = (c < K) ? src[c] : 0.f;
        __nv_bfloat16 h = __float2bfloat16(x);
        row[c]        = h;
        row[Kp + c]   = h;
        row[2*Kp + c] = __float2bfloat16(x - __bfloat162float(h));
    }
}

// ============================================================================
// HMMA GEMM with 3-stage cp.async pipeline.
// 128x128 CTA tile, BK=32, 256 thr = 8 warps, warp tile 64x32 (4x4 m16n8k16).
// Dynamic smem: A[3]|B[3] stages (128 x SROW bf16 each) + bsum.
// ============================================================================
#define SROW 40
#define STG_B (128 * SROW * 2)        /* 10240 bytes per stage per matrix */
#define B_OFF (3 * STG_B)             /* B stages start */
#define BSUM_OFF (6 * STG_B)
#define GEMM_SMEM (BSUM_OFF + 512)

__device__ __forceinline__ void cpasync16(uint32_t saddr, const void* gaddr) {
    asm volatile("cp.async.cg.shared.global [%0], [%1], 16;" :: "r"(saddr), "l"(gaddr));
}
#define CP_COMMIT() asm volatile("cp.async.commit_group;" ::: "memory")
#define CP_WAIT1()  asm volatile("cp.async.wait_group 1;" ::: "memory")

__device__ __forceinline__ void ldsm_x4(uint32_t& r0, uint32_t& r1,
                                        uint32_t& r2, uint32_t& r3, uint32_t a) {
    asm volatile("ldmatrix.sync.aligned.m8n8.x4.shared.b16 {%0,%1,%2,%3}, [%4];"
                 : "=r"(r0), "=r"(r1), "=r"(r2), "=r"(r3) : "r"(a));
}
__device__ __forceinline__ void ldsm_x2(uint32_t& r0, uint32_t& r1, uint32_t a) {
    asm volatile("ldmatrix.sync.aligned.m8n8.x2.shared.b16 {%0,%1}, [%2];"
                 : "=r"(r0), "=r"(r1) : "r"(a));
}
__device__ __forceinline__ void mma16816(float* d, const uint32_t* a, const uint32_t* b) {
    asm volatile("mma.sync.aligned.m16n8k16.row.col.f32.bf16.bf16.f32 "
                 "{%0,%1,%2,%3}, {%4,%5,%6,%7}, {%8,%9}, {%0,%1,%2,%3};"
                 : "+f"(d[0]), "+f"(d[1]), "+f"(d[2]), "+f"(d[3])
                 : "r"(a[0]), "r"(a[1]), "r"(a[2]), "r"(a[3]), "r"(b[0]), "r"(b[1]));
}

__global__ void __launch_bounds__(256)
hmma_gemm(const float* __restrict__ b1, const float* __restrict__ b2, int Kp3)
{
    extern __shared__ __align__(16) char smem[];
    uint32_t sbase = (uint32_t)__cvta_generic_to_shared(smem);
    float* bsum = (float*)(smem + BSUM_OFF);

    const int tid = threadIdx.x, lane = tid & 31, w = tid >> 5;
    const int bn = blockIdx.x, bm = blockIdx.y;
    const int wm = (w & 1) * 64, wn = (w >> 1) * 32;

    if (tid < 128) { int c = bn * 128 + tid; bsum[tid] = b1[c] + b2[c]; }

    const __nv_bfloat16* gA = d_A2 + (size_t)(bm * 128) * Kp3;
    const __nv_bfloat16* gB = d_W2 + (size_t)(bn * 128) * Kp3;

    // loader: 512 uint4 per matrix per stage / 256 thr = 2 each
    const int ar0 = tid >> 2,          ac0 = (tid & 3) * 8;
    const int ar1 = (tid + 256) >> 2,  ac1 = (tid & 3) * 8;

    float acc[4][4][4];
#pragma unroll
    for (int m = 0; m < 4; m++)
#pragma unroll
        for (int n = 0; n < 4; n++)
#pragma unroll
            for (int q = 0; q < 4; q++) acc[m][n][q] = 0.f;

    const int nk = Kp3 / 32;

    // issue loads for one stage
    auto issue = [&](int s, int kb) {
        uint32_t sa = sbase + s * STG_B;
        uint32_t sb = sbase + B_OFF + s * STG_B;
        cpasync16(sa + (ar0 * SROW + ac0) * 2, gA + (size_t)ar0 * Kp3 + kb + ac0);
        cpasync16(sa + (ar1 * SROW + ac1) * 2, gA + (size_t)ar1 * Kp3 + kb + ac1);
        cpasync16(sb + (ar0 * SROW + ac0) * 2, gB + (size_t)ar0 * Kp3 + kb + ac0);
        cpasync16(sb + (ar1 * SROW + ac1) * 2, gB + (size_t)ar1 * Kp3 + kb + ac1);
    };

    issue(0, 0);  CP_COMMIT();
    issue(1, 32); CP_COMMIT();

    int stage = 0;
    for (int kt = 0; kt < nk; kt++) {
        CP_WAIT1();
        __syncthreads();                       // stage `stage` ready, prior mma done
        if (kt + 2 < nk) issue((stage + 2) % 3, (kt + 2) * 32);
        CP_COMMIT();

        const uint32_t bA = sbase + stage * STG_B;
        const uint32_t bB = sbase + B_OFF + stage * STG_B;
#pragma unroll
        for (int ks = 0; ks < 2; ks++) {
            const int k0 = ks * 16;
            uint32_t a[4][4], bf[4][2];
#pragma unroll
            for (int mt = 0; mt < 4; mt++) {
                uint32_t ad = bA + (((wm + mt*16 + (lane & 15)) * SROW
                                     + k0 + (lane >> 4) * 8) << 1);
                ldsm_x4(a[mt][0], a[mt][1], a[mt][2], a[mt][3], ad);
            }
#pragma unroll
            for (int nt = 0; nt < 4; nt++) {
                uint32_t ad = bB + (((wn + nt*8 + (lane & 7)) * SROW
                                     + k0 + ((lane >> 3) & 1) * 8) << 1);
                ldsm_x2(bf[nt][0], bf[nt][1], ad);
            }
#pragma unroll
            for (int mt = 0; mt < 4; mt++)
#pragma unroll
                for (int nt = 0; nt < 4; nt++)
                    mma16816(acc[mt][nt], a[mt], bf[nt]);
        }
        stage = (stage + 1) % 3;
    }

    // epilogue
#pragma unroll
    for (int mt = 0; mt < 4; mt++) {
        int r0 = bm * 128 + wm + mt * 16 + (lane >> 2);
#pragma unroll
        for (int nt = 0; nt < 4; nt++) {
            int c  = wn + nt * 8 + (lane & 3) * 2;
            int cg = bn * 128 + c;
            float2 v0 = make_float2(acc[mt][nt][0] + bsum[c],
                                    acc[mt][nt][1] + bsum[c + 1]);
            float2 v1 = make_float2(acc[mt][nt][2] + bsum[c],
                                    acc[mt][nt][3] + bsum[c + 1]);
            *(float2*)&d_G[(size_t)r0 * GCOLS + cg]       = v0;
            *(float2*)&d_G[(size_t)(r0 + 8) * GCOLS + cg] = v1;
        }
    }
}

// ============================================================================
// Persistent LSTM recurrence. layer 0 writes split-bf16 directly to d_A2
// (layer-1 GEMM input); layer 1 writes fp32 d_Y1 (epilogue input).
// Fast MUFU activations; mapa hoisted out of the loop.
// ============================================================================
__global__ void __cluster_dims__(8,1,1) __launch_bounds__(256,1)
lstm_rec(const float* __restrict__ whh, int layer)
{
    __shared__ __align__(16) float h_sm[2][8][256];
    __shared__ float ps[2][4][8][32];

    const int tid = threadIdx.x;
    const int j  = tid & 31;
    const int g  = (tid >> 5) & 3;
    const int kh = tid >> 7;
    const int hc = blockIdx.x & 7;
    const int cid = blockIdx.x >> 3;
    const int d  = cid & 1;
    const int B0 = (cid >> 1) * 8;

    ulonglong2 w2[32];
    {
        const ulonglong2* wp = (const ulonglong2*)
            (whh + ((size_t)d*1024 + g*256 + hc*32 + j) * 256 + kh*128);
#pragma unroll
        for (int kk = 0; kk < 32; kk++) w2[kk] = wp[kk];
    }
    {
        float* hz = &h_sm[0][0][0];
        for (int i = tid; i < 2*8*256; i += 256) hz[i] = 0.f;
    }
    const int ub = tid >> 5, uj = tid & 31;
    float creg = 0.f;
    __syncthreads();
    asm volatile("barrier.cluster.arrive.aligned;" ::: "memory");
    asm volatile("barrier.cluster.wait.aligned;"   ::: "memory");

    uint32_t base_l0 = (uint32_t)__cvta_generic_to_shared(&h_sm[0][ub][hc*32+uj]);
    uint32_t base_l1 = (uint32_t)__cvta_generic_to_shared(&h_sm[1][ub][hc*32+uj]);
    const uint32_t delta = base_l1 - base_l0;   // same offset in every peer CTA
    uint32_t ra[8];
#pragma unroll
    for (unsigned r = 0; r < 8; r++)
        asm volatile("mapa.shared::cluster.u32 %0, %1, %2;"
                     : "=r"(ra[r]) : "r"(base_l0), "r"(r));
    const int kq0 = kh * 32;
    const int col = d*256 + hc*32 + uj;         // output column (0..511)

    for (int t = 0; t < SEQ; t++) {
        const int p = t & 1;
        size_t gb = ((size_t)t*64 + B0 + ub) * GCOLS + (size_t)d*1024 + hc*32 + uj;
        float gp0 = d_G[gb];
        float gp1 = d_G[gb + 256];
        float gp2 = d_G[gb + 512];
        float gp3 = d_G[gb + 768];

        const ulonglong2* hb = (const ulonglong2*)&h_sm[p][0][0];
        unsigned long long acc2[8];
#pragma unroll
        for (int b = 0; b < 8; b++) acc2[b] = 0ull;
#pragma unroll
        for (int kk = 0; kk < 32; kk++) {
            ulonglong2 wv = w2[kk];
#pragma unroll
            for (int b = 0; b < 8; b++) {
                ulonglong2 hv = hb[b*64 + kq0 + kk];
                fma2(acc2[b], wv.x, hv.x);
                fma2(acc2[b], wv.y, hv.y);
            }
        }
#pragma unroll
        for (int b = 0; b < 8; b++) {
            float2 u = unpk(acc2[b]);
            ps[kh][g][b][j] = u.x + u.y;
        }
        __syncthreads();

        float si = ps[0][0][ub][uj] + ps[1][0][ub][uj] + gp0;
        float sf = ps[0][1][ub][uj] + ps[1][1][ub][uj] + gp1;
        float sg = ps[0][2][ub][uj] + ps[1][2][ub][uj] + gp2;
        float so = ps[0][3][ub][uj] + ps[1][3][ub][uj] + gp3;
        float iv = fsigm(si);
        float fv = fsigm(sf);
        float ov = fsigm(so);
        creg = fv * creg + iv * ftanh(sg);
        float hnew = ov * ftanh(creg);

        size_t orow = (size_t)t*64 + B0 + ub;
        if (layer == 0) {
            __nv_bfloat16 hh = __float2bfloat16(hnew);
            __nv_bfloat16 hl = __float2bfloat16(hnew - __bfloat162float(hh));
            __nv_bfloat16* arow = d_A2 + orow * 1536;
            arow[col]        = hh;
            arow[512 + col]  = hl;
            arow[1024 + col] = hh;
        } else {
            d_Y1[orow * 512 + col] = hnew;
        }

        // push hnew into next-parity buffer of ALL cluster CTAs (incl. self)
        uint32_t off = p ? 0u : delta;
#pragma unroll
        for (unsigned r = 0; r < 8; r++)
            asm volatile("st.shared::cluster.f32 [%0], %1;"
                         :: "r"(ra[r] + off), "f"(hnew) : "memory");
        asm volatile("barrier.cluster.arrive.aligned;" ::: "memory");
        asm volatile("barrier.cluster.wait.aligned;"   ::: "memory");
    }
}

// ============================================================================
// Epilogue: gather at positions, classifier, sigmoid.
// out layout: logits(64x2) | probs(64x2) | target(64x512)
// ============================================================================
__global__ void __launch_bounds__(512)
epilogue(const int* __restrict__ pos, const float* __restrict__ wcls,
         const float* __restrict__ bcls, float* __restrict__ out)
{
    __shared__ float s0[512], s1[512];
    int b = blockIdx.x, i = threadIdx.x;
    int t = pos[b];
    float y = d_Y1[((size_t)t*64 + b) * 512 + i];
    out[256 + b*512 + i] = y;
    s0[i] = y * wcls[i];
    s1[i] = y * wcls[512 + i];
    __syncthreads();
    for (int st = 256; st > 0; st >>= 1) {
        if (i < st) { s0[i] += s0[i+st]; s1[i] += s1[i+st]; }
        __syncthreads();
    }
    if (i == 0) {
        float l0 = s0[0] + bcls[0], l1 = s1[0] + bcls[1];
        out[b*2+0] = l0;            out[b*2+1] = l1;
        out[128 + b*2+0] = 1.f/(1.f+expf(-l0));
        out[128 + b*2+1] = 1.f/(1.f+expf(-l1));
    }
}

// ============================================================================
extern "C" void kernel_launch(void* const* d_in, const int* in_sizes, int n_in,
                              void* d_out, int out_size)
{
    const float *emb=0,*wih0=0,*whh0=0,*bih0=0,*bhh0=0;
    const float *wih1=0,*whh1=0,*bih1=0,*bhh1=0,*wcls=0,*bcls=0;
    const int *ctx=0,*pos=0;
    int nwhh = 0, nb = 0;
    for (int i = 0; i < n_in; i++) {
        int s = in_sizes[i]; const void* p = d_in[i];
        switch (s) {
            case 30000000: emb  = (const float*)p; break;
            case 614400:   wih0 = (const float*)p; break;
            case 1048576:  wih1 = (const float*)p; break;
            case 524288:   if (nwhh++ == 0) whh0 = (const float*)p;
                           else             whh1 = (const float*)p; break;
            case 2048:     if (nb == 0) bih0 = (const float*)p;
                           else if (nb == 1) bhh0 = (const float*)p;
                           else if (nb == 2) bih1 = (const float*)p;
                           else              bhh1 = (const float*)p;
                           nb++; break;
            case 1024:     wcls = (const float*)p; break;
            case 2:        bcls = (const float*)p; break;
            case 32768:    ctx  = (const int*)p; break;
            case 64:       pos  = (const int*)p; break;
            default: break;
        }
    }

    cudaFuncSetAttribute(hmma_gemm, cudaFuncAttributeMaxDynamicSharedMemorySize, GEMM_SMEM);

    dim3 ggrid(16, 256);
    // layer 0
    conv_a<<<NROWS, 128>>>(emb, ctx);
    conv_w<<<GCOLS, 128>>>(wih0, 0);
    hmma_gemm<<<ggrid, 256, GEMM_SMEM>>>(bih0, bhh0, 960);
    lstm_rec<<<128, 256>>>(whh0, 0);          // writes d_A2 (layer-1 input)
    // layer 1
    conv_w<<<GCOLS, 128>>>(wih1, 1);
    hmma_gemm<<<ggrid, 256, GEMM_SMEM>>>(bih1, bhh1, 1536);
    lstm_rec<<<128, 256>>>(whh1, 1);          // writes d_Y1
    // classifier
    epilogue<<<64, 512>>>(pos, wcls, bcls, (float*)d_out);
}

// round 11
// speedup vs baseline: 1.4026x; 1.4026x over previous
#include <cuda_runtime.h>
#include <cuda_bf16.h>
#include <math.h>
#include <stdint.h>

#define VOCAB 100000
#define EMB   300
#define HID   256
#define BATCH 64
#define SEQ   512
#define NROWS (SEQ*BATCH)   /* 32768 */
#define GCOLS 2048          /* 2 dirs * 4 gates * 256 */
#define K3MAX 1536          /* max concatenated K (layer 1: 3*512) */

// ---------------- static scratch (no allocations allowed) -------------------
__device__ float d_G [(size_t)NROWS * GCOLS];     // gate preactivations
__device__ float d_Y1[(size_t)NROWS * 512];       // layer-1 output (t,b,2H)
__device__ __nv_bfloat16 d_A2[(size_t)NROWS * K3MAX];  // [Ahi|Alo|Ahi]
__device__ __nv_bfloat16 d_W2[(size_t)GCOLS * K3MAX];  // [Whi|Whi|Wlo]

// ---------------- packed fp32x2 helpers -------------------------------------
__device__ __forceinline__ void fma2(unsigned long long& acc,
                                     unsigned long long a, unsigned long long b) {
    asm("fma.rn.f32x2 %0, %1, %2, %0;" : "+l"(acc) : "l"(a), "l"(b));
}
__device__ __forceinline__ float2 unpk(unsigned long long v) {
    float2 f;
    asm("mov.b64 {%0, %1}, %2;" : "=f"(f.x), "=f"(f.y) : "l"(v));
    return f;
}
__device__ __forceinline__ float fsigm(float x) {
    return __fdividef(1.f, 1.f + __expf(-x));
}
__device__ __forceinline__ float ftanh(float x) {
    return __fdividef(2.f, 1.f + __expf(-2.f * x)) - 1.f;
}

// ============================================================================
// conv_a: layer-0 input — emb gather -> split bf16 [hi|lo|hi], Kp=320, stride 960
// ============================================================================
__global__ void conv_a(const float* __restrict__ emb, const int* __restrict__ tokens)
{
    int r = blockIdx.x;                    // r = t*64 + b
    int b = r & 63, t = r >> 6;
    const float* src = emb + (size_t)tokens[b * SEQ + t] * EMB;
    __nv_bfloat16* row = d_A2 + (size_t)r * 960;
    for (int c = threadIdx.x; c < 320; c += blockDim.x) {
        float x = (c < EMB) ? src[c] : 0.f;
        __nv_bfloat16 h = __float2bfloat16(x);
        row[c]       = h;
        row[320 + c] = __float2bfloat16(x - __bfloat162float(h));
        row[640 + c] = h;
    }
}

__global__ void conv_w(const float* __restrict__ w, int layer)
{
    int r = blockIdx.x;                    // gate-column index (2048)
    int K, Kp, stride;
    if (layer == 0) { K = 300; Kp = 320; stride = 960; }
    else            { K = 512; Kp = 512; stride = 1536; }
    const float* src = w + (size_t)r * K;
    __nv_bfloat16* row = d_W2 + (size_t)r * stride;
    for (int c = threadIdx.x; c < Kp; c += blockDim.x) {
        float x = (c < K) ? src[c] : 0.f;
        __nv_bfloat16 h = __float2bfloat16(x);
        row[c]        = h;
        row[Kp + c]   = h;
        row[2*Kp + c] = __float2bfloat16(x - __bfloat162float(h));
    }
}

// ============================================================================
// HMMA GEMM with 3-stage cp.async pipeline (frozen from R10).
// ============================================================================
#define SROW 40
#define STG_B (128 * SROW * 2)
#define B_OFF (3 * STG_B)
#define BSUM_OFF (6 * STG_B)
#define GEMM_SMEM (BSUM_OFF + 512)

__device__ __forceinline__ void cpasync16(uint32_t saddr, const void* gaddr) {
    asm volatile("cp.async.cg.shared.global [%0], [%1], 16;" :: "r"(saddr), "l"(gaddr));
}
#define CP_COMMIT() asm volatile("cp.async.commit_group;" ::: "memory")
#define CP_WAIT1()  asm volatile("cp.async.wait_group 1;" ::: "memory")

__device__ __forceinline__ void ldsm_x4(uint32_t& r0, uint32_t& r1,
                                        uint32_t& r2, uint32_t& r3, uint32_t a) {
    asm volatile("ldmatrix.sync.aligned.m8n8.x4.shared.b16 {%0,%1,%2,%3}, [%4];"
                 : "=r"(r0), "=r"(r1), "=r"(r2), "=r"(r3) : "r"(a));
}
__device__ __forceinline__ void ldsm_x2(uint32_t& r0, uint32_t& r1, uint32_t a) {
    asm volatile("ldmatrix.sync.aligned.m8n8.x2.shared.b16 {%0,%1}, [%2];"
                 : "=r"(r0), "=r"(r1) : "r"(a));
}
__device__ __forceinline__ void mma16816(float* d, const uint32_t* a, const uint32_t* b) {
    asm volatile("mma.sync.aligned.m16n8k16.row.col.f32.bf16.bf16.f32 "
                 "{%0,%1,%2,%3}, {%4,%5,%6,%7}, {%8,%9}, {%0,%1,%2,%3};"
                 : "+f"(d[0]), "+f"(d[1]), "+f"(d[2]), "+f"(d[3])
                 : "r"(a[0]), "r"(a[1]), "r"(a[2]), "r"(a[3]), "r"(b[0]), "r"(b[1]));
}

__global__ void __launch_bounds__(256)
hmma_gemm(const float* __restrict__ b1, const float* __restrict__ b2, int Kp3)
{
    extern __shared__ __align__(16) char smem[];
    uint32_t sbase = (uint32_t)__cvta_generic_to_shared(smem);
    float* bsum = (float*)(smem + BSUM_OFF);

    const int tid = threadIdx.x, lane = tid & 31, w = tid >> 5;
    const int bn = blockIdx.x, bm = blockIdx.y;
    const int wm = (w & 1) * 64, wn = (w >> 1) * 32;

    if (tid < 128) { int c = bn * 128 + tid; bsum[tid] = b1[c] + b2[c]; }

    const __nv_bfloat16* gA = d_A2 + (size_t)(bm * 128) * Kp3;
    const __nv_bfloat16* gB = d_W2 + (size_t)(bn * 128) * Kp3;

    const int ar0 = tid >> 2,          ac0 = (tid & 3) * 8;
    const int ar1 = (tid + 256) >> 2,  ac1 = (tid & 3) * 8;

    float acc[4][4][4];
#pragma unroll
    for (int m = 0; m < 4; m++)
#pragma unroll
        for (int n = 0; n < 4; n++)
#pragma unroll
            for (int q = 0; q < 4; q++) acc[m][n][q] = 0.f;

    const int nk = Kp3 / 32;

    auto issue = [&](int s, int kb) {
        uint32_t sa = sbase + s * STG_B;
        uint32_t sb = sbase + B_OFF + s * STG_B;
        cpasync16(sa + (ar0 * SROW + ac0) * 2, gA + (size_t)ar0 * Kp3 + kb + ac0);
        cpasync16(sa + (ar1 * SROW + ac1) * 2, gA + (size_t)ar1 * Kp3 + kb + ac1);
        cpasync16(sb + (ar0 * SROW + ac0) * 2, gB + (size_t)ar0 * Kp3 + kb + ac0);
        cpasync16(sb + (ar1 * SROW + ac1) * 2, gB + (size_t)ar1 * Kp3 + kb + ac1);
    };

    issue(0, 0);  CP_COMMIT();
    issue(1, 32); CP_COMMIT();

    int stage = 0;
    for (int kt = 0; kt < nk; kt++) {
        CP_WAIT1();
        __syncthreads();
        if (kt + 2 < nk) issue((stage + 2) % 3, (kt + 2) * 32);
        CP_COMMIT();

        const uint32_t bA = sbase + stage * STG_B;
        const uint32_t bB = sbase + B_OFF + stage * STG_B;
#pragma unroll
        for (int ks = 0; ks < 2; ks++) {
            const int k0 = ks * 16;
            uint32_t a[4][4], bf[4][2];
#pragma unroll
            for (int mt = 0; mt < 4; mt++) {
                uint32_t ad = bA + (((wm + mt*16 + (lane & 15)) * SROW
                                     + k0 + (lane >> 4) * 8) << 1);
                ldsm_x4(a[mt][0], a[mt][1], a[mt][2], a[mt][3], ad);
            }
#pragma unroll
            for (int nt = 0; nt < 4; nt++) {
                uint32_t ad = bB + (((wn + nt*8 + (lane & 7)) * SROW
                                     + k0 + ((lane >> 3) & 1) * 8) << 1);
                ldsm_x2(bf[nt][0], bf[nt][1], ad);
            }
#pragma unroll
            for (int mt = 0; mt < 4; mt++)
#pragma unroll
                for (int nt = 0; nt < 4; nt++)
                    mma16816(acc[mt][nt], a[mt], bf[nt]);
        }
        stage = (stage + 1) % 3;
    }

#pragma unroll
    for (int mt = 0; mt < 4; mt++) {
        int r0 = bm * 128 + wm + mt * 16 + (lane >> 2);
#pragma unroll
        for (int nt = 0; nt < 4; nt++) {
            int c  = wn + nt * 8 + (lane & 3) * 2;
            int cg = bn * 128 + c;
            float2 v0 = make_float2(acc[mt][nt][0] + bsum[c],
                                    acc[mt][nt][1] + bsum[c + 1]);
            float2 v1 = make_float2(acc[mt][nt][2] + bsum[c],
                                    acc[mt][nt][3] + bsum[c + 1]);
            *(float2*)&d_G[(size_t)r0 * GCOLS + cg]       = v0;
            *(float2*)&d_G[(size_t)(r0 + 8) * GCOLS + cg] = v1;
        }
    }
}

// ============================================================================
// Persistent LSTM recurrence, v2: 4-gate column reuse per h-read.
// Thread (j0=tid&31, kg=tid>>5) owns W_hh[d][g*256+hc*32+j0][kg*32..+32) for
// ALL 4 gates (128 regs). Dot phase: each 16B h-load feeds 8 FFMA2 (4 gates x
// f32x2) -> smem traffic 256KB/step/CTA (was 1MB). 8-way k-group partials in
// ps[8][4][8][32]; update thread (b=kg, col=j0) reduces, applies activations.
// h exchanged via DSMEM push + 1 cluster barrier/step.
// ============================================================================
#define LSTM_SMEM (2*8*256*4 + 8*4*8*32*4)   /* 16KB h + 32KB ps = 49152 */

__global__ void __cluster_dims__(8,1,1) __launch_bounds__(256,1)
lstm_rec(const float* __restrict__ whh, int layer)
{
    extern __shared__ __align__(16) float dsm[];
    float (*h_sm)[8][256]   = (float(*)[8][256])dsm;                 // [2][8][256]
    float (*ps)[4][8][32]   = (float(*)[4][8][32])(dsm + 2*8*256);   // [8][4][8][32]

    const int tid = threadIdx.x;
    const int j0  = tid & 31;        // h-col within 32 (also update col)
    const int kg  = tid >> 5;        // k-group (0..7)   (also update batch)
    const int hc  = blockIdx.x & 7;
    const int cid = blockIdx.x >> 3;
    const int d   = cid & 1;
    const int B0  = (cid >> 1) * 8;

    // weights: 4 gates x 8 ulonglong2 (32 k-floats each) = 128 regs
    ulonglong2 w2[4][8];
#pragma unroll
    for (int g = 0; g < 4; g++) {
        const ulonglong2* wp = (const ulonglong2*)
            (whh + ((size_t)d*1024 + g*256 + hc*32 + j0) * 256 + kg*32);
#pragma unroll
        for (int i = 0; i < 8; i++) w2[g][i] = wp[i];
    }
    // zero both h buffers
    for (int i = tid; i < 2*8*256; i += 256) dsm[i] = 0.f;
    float creg = 0.f;
    __syncthreads();
    asm volatile("barrier.cluster.arrive.aligned;" ::: "memory");
    asm volatile("barrier.cluster.wait.aligned;"   ::: "memory");

    uint32_t base_l0 = (uint32_t)__cvta_generic_to_shared(&h_sm[0][kg][hc*32+j0]);
    uint32_t base_l1 = (uint32_t)__cvta_generic_to_shared(&h_sm[1][kg][hc*32+j0]);
    const uint32_t delta = base_l1 - base_l0;
    uint32_t ra[8];
#pragma unroll
    for (unsigned r = 0; r < 8; r++)
        asm volatile("mapa.shared::cluster.u32 %0, %1, %2;"
                     : "=r"(ra[r]) : "r"(base_l0), "r"(r));
    const int col = d*256 + hc*32 + j0;          // output column (0..511)

    for (int t = 0; t < SEQ; t++) {
        const int p = t & 1;
        // prefetch gate preactivations for update owner (b=kg, col=j0)
        size_t gb = ((size_t)t*64 + B0 + kg) * GCOLS + (size_t)d*1024 + hc*32 + j0;
        float gp0 = d_G[gb];
        float gp1 = d_G[gb + 256];
        float gp2 = d_G[gb + 512];
        float gp3 = d_G[gb + 768];

        // dot phase: 8 batches, 4 gates, 32 k each
#pragma unroll 2
        for (int b = 0; b < 8; b++) {
            const ulonglong2* hr = (const ulonglong2*)&h_sm[p][b][kg*32];
            unsigned long long a0 = 0ull, a1 = 0ull, a2 = 0ull, a3 = 0ull;
#pragma unroll
            for (int i = 0; i < 8; i++) {
                ulonglong2 hv = hr[i];
                fma2(a0, w2[0][i].x, hv.x); fma2(a0, w2[0][i].y, hv.y);
                fma2(a1, w2[1][i].x, hv.x); fma2(a1, w2[1][i].y, hv.y);
                fma2(a2, w2[2][i].x, hv.x); fma2(a2, w2[2][i].y, hv.y);
                fma2(a3, w2[3][i].x, hv.x); fma2(a3, w2[3][i].y, hv.y);
            }
            float2 u0 = unpk(a0), u1 = unpk(a1), u2 = unpk(a2), u3 = unpk(a3);
            ps[kg][0][b][j0] = u0.x + u0.y;
            ps[kg][1][b][j0] = u1.x + u1.y;
            ps[kg][2][b][j0] = u2.x + u2.y;
            ps[kg][3][b][j0] = u3.x + u3.y;
        }
        __syncthreads();

        // update phase: reduce 8 k-groups, activations
        float si = gp0, sf = gp1, sg = gp2, so = gp3;
#pragma unroll
        for (int kq = 0; kq < 8; kq++) {
            si += ps[kq][0][kg][j0];
            sf += ps[kq][1][kg][j0];
            sg += ps[kq][2][kg][j0];
            so += ps[kq][3][kg][j0];
        }
        float iv = fsigm(si);
        float fv = fsigm(sf);
        float ov = fsigm(so);
        creg = fv * creg + iv * ftanh(sg);
        float hnew = ov * ftanh(creg);

        size_t orow = (size_t)t*64 + B0 + kg;
        if (layer == 0) {
            __nv_bfloat16 hh = __float2bfloat16(hnew);
            __nv_bfloat16 hl = __float2bfloat16(hnew - __bfloat162float(hh));
            __nv_bfloat16* arow = d_A2 + orow * 1536;
            arow[col]        = hh;
            arow[512 + col]  = hl;
            arow[1024 + col] = hh;
        } else {
            d_Y1[orow * 512 + col] = hnew;
        }

        // push hnew into next-parity buffer of ALL cluster CTAs (incl. self)
        uint32_t off = p ? 0u : delta;
#pragma unroll
        for (unsigned r = 0; r < 8; r++)
            asm volatile("st.shared::cluster.f32 [%0], %1;"
                         :: "r"(ra[r] + off), "f"(hnew) : "memory");
        asm volatile("barrier.cluster.arrive.aligned;" ::: "memory");
        asm volatile("barrier.cluster.wait.aligned;"   ::: "memory");
    }
}

// ============================================================================
// Epilogue: gather at positions, classifier, sigmoid.
// out layout: logits(64x2) | probs(64x2) | target(64x512)
// ============================================================================
__global__ void __launch_bounds__(512)
epilogue(const int* __restrict__ pos, const float* __restrict__ wcls,
         const float* __restrict__ bcls, float* __restrict__ out)
{
    __shared__ float s0[512], s1[512];
    int b = blockIdx.x, i = threadIdx.x;
    int t = pos[b];
    float y = d_Y1[((size_t)t*64 + b) * 512 + i];
    out[256 + b*512 + i] = y;
    s0[i] = y * wcls[i];
    s1[i] = y * wcls[512 + i];
    __syncthreads();
    for (int st = 256; st > 0; st >>= 1) {
        if (i < st) { s0[i] += s0[i+st]; s1[i] += s1[i+st]; }
        __syncthreads();
    }
    if (i == 0) {
        float l0 = s0[0] + bcls[0], l1 = s1[0] + bcls[1];
        out[b*2+0] = l0;            out[b*2+1] = l1;
        out[128 + b*2+0] = 1.f/(1.f+expf(-l0));
        out[128 + b*2+1] = 1.f/(1.f+expf(-l1));
    }
}

// ============================================================================
extern "C" void kernel_launch(void* const* d_in, const int* in_sizes, int n_in,
                              void* d_out, int out_size)
{
    const float *emb=0,*wih0=0,*whh0=0,*bih0=0,*bhh0=0;
    const float *wih1=0,*whh1=0,*bih1=0,*bhh1=0,*wcls=0,*bcls=0;
    const int *ctx=0,*pos=0;
    int nwhh = 0, nb = 0;
    for (int i = 0; i < n_in; i++) {
        int s = in_sizes[i]; const void* p = d_in[i];
        switch (s) {
            case 30000000: emb  = (const float*)p; break;
            case 614400:   wih0 = (const float*)p; break;
            case 1048576:  wih1 = (const float*)p; break;
            case 524288:   if (nwhh++ == 0) whh0 = (const float*)p;
                           else             whh1 = (const float*)p; break;
            case 2048:     if (nb == 0) bih0 = (const float*)p;
                           else if (nb == 1) bhh0 = (const float*)p;
                           else if (nb == 2) bih1 = (const float*)p;
                           else              bhh1 = (const float*)p;
                           nb++; break;
            case 1024:     wcls = (const float*)p; break;
            case 2:        bcls = (const float*)p; break;
            case 32768:    ctx  = (const int*)p; break;
            case 64:       pos  = (const int*)p; break;
            default: break;
        }
    }

    cudaFuncSetAttribute(hmma_gemm, cudaFuncAttributeMaxDynamicSharedMemorySize, GEMM_SMEM);
    cudaFuncSetAttribute(lstm_rec,  cudaFuncAttributeMaxDynamicSharedMemorySize, LSTM_SMEM);

    dim3 ggrid(16, 256);
    // layer 0
    conv_a<<<NROWS, 128>>>(emb, ctx);
    conv_w<<<GCOLS, 128>>>(wih0, 0);
    hmma_gemm<<<ggrid, 256, GEMM_SMEM>>>(bih0, bhh0, 960);
    lstm_rec<<<128, 256, LSTM_SMEM>>>(whh0, 0);   // writes d_A2 (layer-1 input)
    // layer 1
    conv_w<<<GCOLS, 128>>>(wih1, 1);
    hmma_gemm<<<ggrid, 256, GEMM_SMEM>>>(bih1, bhh1, 1536);
    lstm_rec<<<128, 256, LSTM_SMEM>>>(whh1, 1);   // writes d_Y1
    // classifier
    epilogue<<<64, 512>>>(pos, wcls, bcls, (float*)d_out);
}